// round 12
// baseline (speedup 1.0000x reference)
#include <cuda_runtime.h>
#include <cstddef>

#define NUM_CLASSES 1000000
#define FEAT_DIM    128
#define BATCH       16384
#define ALPHA       0.5f

#define N_ELEMS   ((size_t)NUM_CLASSES * FEAT_DIM)   // 128,000,000
#define N_QUADS   (N_ELEMS / 4)                       // 32,000,000
#define N_GROUPS  (N_QUADS / 4)                       // 8,000,000 (4 quads/thread)

// Scratch. .bss => zero-initialized at load; clean-on-exit in k_update
// restores zeroed state for the next graph replay.
__device__ float  g_sums[N_ELEMS];      // 512 MB static bss
__device__ float  g_counts[NUM_CLASSES];
__device__ int    g_owner[BATCH];       // 1 if batch elem is unique owner of its label
__device__ double g_loss;

// ---------------------------------------------------------------------------
// K1 (side stream, overlapped with the copy): scatter features into per-class
// sums + counts, accumulate loss (block reduction -> 1 double atomic/block),
// elect one owner warp per distinct label.
// One warp per batch element; lane k owns feature quad k.
// ---------------------------------------------------------------------------
__global__ void k_accum(const float* __restrict__ features,
                        const float* __restrict__ centers,
                        const int*   __restrict__ labels)
{
    const int gid  = blockIdx.x * blockDim.x + threadIdx.x;
    const int w    = gid >> 5;
    const int lane = gid & 31;
    const int wib  = threadIdx.x >> 5;

    __shared__ float s_part[8];

    float v = 0.0f;
    if (w < BATCH) {
        const int l = labels[w];
        const float4 f = reinterpret_cast<const float4*>(features)[(size_t)w * 32 + lane];
        const float4 c = reinterpret_cast<const float4*>(centers )[(size_t)l * 32 + lane];

        float* srow = g_sums + (size_t)l * FEAT_DIM + lane * 4;
        atomicAdd(srow + 0, f.x);
        atomicAdd(srow + 1, f.y);
        atomicAdd(srow + 2, f.z);
        atomicAdd(srow + 3, f.w);
        if (lane == 0) {
            const float old = atomicAdd(&g_counts[l], 1.0f);
            g_owner[w] = (old == 0.0f) ? 1 : 0;
        }

        const float dx = f.x - c.x, dy = f.y - c.y, dz = f.z - c.z, dw = f.w - c.w;
        v = dx * dx + dy * dy + dz * dz + dw * dw;
    }

    #pragma unroll
    for (int o = 16; o > 0; o >>= 1)
        v += __shfl_down_sync(0xffffffffu, v, o);
    if (lane == 0) s_part[wib] = v;
    __syncthreads();
    if (threadIdx.x == 0) {
        float tot = 0.0f;
        #pragma unroll
        for (int i = 0; i < 8; i++) tot += s_part[i];
        atomicAdd(&g_loss, (double)tot);
    }
}

// ---------------------------------------------------------------------------
// K2: PURE bulk shifted copy, 4 quads (64 B) per thread: 4 front-batched
// LDG.128 for deep MLP, one shfl per thread (3 of 4 straddles are free
// intra-thread register moves). Thread p owns src quads 4p..4p+3
// (elems 16p..16p+15) and produces dst quads 4p..4p+3:
//   dst[4p]   = { c[16p-1], b0.xyz }   (straddle: prev thread's b3.w / shfl)
//   dst[4p+1] = { b0.w, b1.xyz }
//   dst[4p+2] = { b1.w, b2.xyz }
//   dst[4p+3] = { b2.w, b3.xyz }
// Evict-first hints: the 1 GB stream is touch-once.
// p==0 writes head out[1..3] and tail out[N].
// ---------------------------------------------------------------------------
__global__ void k_copy(const float* __restrict__ c, float* __restrict__ out)
{
    const size_t p = (size_t)blockIdx.x * blockDim.x + threadIdx.x;  // group idx
    const float4* src = reinterpret_cast<const float4*>(c) + 4 * p;
    const float4 b0 = __ldcs(src + 0);
    const float4 b1 = __ldcs(src + 1);
    const float4 b2 = __ldcs(src + 2);
    const float4 b3 = __ldcs(src + 3);

    float pw = __shfl_up_sync(0xffffffffu, b3.w, 1);   // prev thread's last elem
    if ((threadIdx.x & 31) == 0 && p > 0)
        pw = __ldg(c + 16 * p - 1);

    float4* dst = reinterpret_cast<float4*>(out) + 4 * p;
    if (p == 0) {
        out[1] = b0.x; out[2] = b0.y; out[3] = b0.z;
        out[N_ELEMS] = c[N_ELEMS - 1];                 // tail element
    } else {
        __stcs(dst + 0, make_float4(pw, b0.x, b0.y, b0.z));
    }
    __stcs(dst + 1, make_float4(b0.w, b1.x, b1.y, b1.z));
    __stcs(dst + 2, make_float4(b1.w, b2.x, b2.y, b2.z));
    __stcs(dst + 3, make_float4(b2.w, b3.x, b3.y, b3.z));
}

// ---------------------------------------------------------------------------
// K3 (after join): owner warps overwrite their class row with the momentum
// update using dst-ALIGNED float4 stores. Lane k computes val = elems
// 4k..4k+3 and stores out quad (32l + k) = {val[4k-1] via shfl, val[4k..4k+2]}
// covering out[128l+4k .. +3] = row elems 4k-1..4k+2. Lane 0 skips the vector
// store and writes elems 0..2 scalar; lane 31 writes elem 127 scalar.
// Coverage: 0..2 | 3..126 | 127 — complete, disjoint from neighboring rows.
// Then CLEAR the scratch consumed. Thread 0 emits loss + resets accumulator.
//   new_c = (1-ALPHA)*c + (ALPHA/cnt)*sum
// ---------------------------------------------------------------------------
__global__ void k_update(const float* __restrict__ centers,
                         const int*   __restrict__ labels,
                         float*       __restrict__ out)
{
    const int gid  = blockIdx.x * blockDim.x + threadIdx.x;
    const int w    = gid >> 5;
    const int lane = gid & 31;

    if (gid == 0) {
        out[0] = (float)(g_loss / (2.0 * (double)BATCH));
        g_loss = 0.0;
    }
    if (w >= BATCH) return;
    if (!g_owner[w]) return;                 // warp-uniform branch

    const int l = labels[w];
    const float cnt = g_counts[l];
    const float k1  = 1.0f - ALPHA;
    const float k2  = ALPHA / fmaxf(cnt, 1.0f);

    const size_t q = (size_t)l * 32 + lane;
    const float4 c = reinterpret_cast<const float4*>(centers)[q];
    const float4 s = reinterpret_cast<const float4*>(g_sums)[q];

    float4 val;
    val.x = k1 * c.x + k2 * s.x;
    val.y = k1 * c.y + k2 * s.y;
    val.z = k1 * c.z + k2 * s.z;
    val.w = k1 * c.w + k2 * s.w;

    const float pw = __shfl_up_sync(0xffffffffu, val.w, 1);  // val[4k-1]

    const size_t row = 1 + (size_t)l * FEAT_DIM;             // out[] index of elem 0
    if (lane == 0) {
        out[row + 0] = val.x;                                 // elems 0,1,2
        out[row + 1] = val.y;
        out[row + 2] = val.z;
    } else {
        reinterpret_cast<float4*>(out)[q] =
            make_float4(pw, val.x, val.y, val.z);
    }
    if (lane == 31)
        out[row + 127] = val.w;                               // elem 127

    // clean-on-exit: restore zeroed scratch for the next replay
    reinterpret_cast<float4*>(g_sums)[q] = make_float4(0.f, 0.f, 0.f, 0.f);
    if (lane == 0) {
        g_counts[l] = 0.0f;
        g_owner[w]  = 0;
    }
}

// ---------------------------------------------------------------------------
// R7 topology (proven best): accum on a high-priority side stream concurrent
// with the single bulk copy; join; one update. All capture-safe.
// ---------------------------------------------------------------------------
extern "C" void kernel_launch(void* const* d_in, const int* in_sizes, int n_in,
                              void* d_out, int out_size)
{
    const float* features = (const float*)d_in[0];
    const float* centers  = (const float*)d_in[1];
    const int*   labels   = (const int*)d_in[2];
    float*       out      = (float*)d_out;

    (void)in_sizes; (void)n_in; (void)out_size;

    const int warps_grid = (BATCH * 32) / 256;          // 2048 blocks of 256

    int prLo = 0, prHi = 0;
    cudaDeviceGetStreamPriorityRange(&prLo, &prHi);

    cudaStream_t s2;
    cudaEvent_t  eFork, eJoin;
    cudaStreamCreateWithPriority(&s2, cudaStreamNonBlocking, prHi);
    cudaEventCreateWithFlags(&eFork, cudaEventDisableTiming);
    cudaEventCreateWithFlags(&eJoin, cudaEventDisableTiming);

    // fork: side stream joins the capture graph via the event dependency
    cudaEventRecord(eFork, 0);
    cudaStreamWaitEvent(s2, eFork, 0);

    k_accum<<<warps_grid, 256, 0, s2>>>(features, centers, labels);     // side
    k_copy <<<(int)(N_GROUPS / 256), 256>>>(centers, out);              // main, 31,250 blocks

    // join: main stream waits for accum before the update
    cudaEventRecord(eJoin, s2);
    cudaStreamWaitEvent(0, eJoin, 0);

    k_update<<<warps_grid, 256>>>(centers, labels, out);

    cudaEventDestroy(eFork);
    cudaEventDestroy(eJoin);
    cudaStreamDestroy(s2);
}

// round 13
// speedup vs baseline: 1.1289x; 1.1289x over previous
#include <cuda_runtime.h>
#include <cstddef>

#define NUM_CLASSES 1000000
#define FEAT_DIM    128
#define BATCH       16384
#define ALPHA       0.5f

#define N_ELEMS   ((size_t)NUM_CLASSES * FEAT_DIM)   // 128,000,000
#define N_QUADS   (N_ELEMS / 4)                       // 32,000,000
#define N_CWARPS  (N_QUADS / 64)                      // 500,000 copy warps

// Scratch. .bss => zero-initialized at load; clean-on-exit in k_update
// restores zeroed state for the next graph replay.
__device__ float  g_sums[N_ELEMS];      // 512 MB static bss
__device__ float  g_counts[NUM_CLASSES];
__device__ int    g_owner[BATCH];       // 1 if batch elem is unique owner of its label
__device__ double g_loss;

// ---------------------------------------------------------------------------
// K1 (side stream, overlapped with the copy): scatter features into per-class
// sums + counts, accumulate loss (block reduction -> 1 double atomic/block),
// elect one owner warp per distinct label.
// One warp per batch element; lane k owns feature quad k.
// ---------------------------------------------------------------------------
__global__ void k_accum(const float* __restrict__ features,
                        const float* __restrict__ centers,
                        const int*   __restrict__ labels)
{
    const int gid  = blockIdx.x * blockDim.x + threadIdx.x;
    const int w    = gid >> 5;
    const int lane = gid & 31;
    const int wib  = threadIdx.x >> 5;

    __shared__ float s_part[8];

    float v = 0.0f;
    if (w < BATCH) {
        const int l = labels[w];
        const float4 f = reinterpret_cast<const float4*>(features)[(size_t)w * 32 + lane];
        const float4 c = reinterpret_cast<const float4*>(centers )[(size_t)l * 32 + lane];

        float* srow = g_sums + (size_t)l * FEAT_DIM + lane * 4;
        atomicAdd(srow + 0, f.x);
        atomicAdd(srow + 1, f.y);
        atomicAdd(srow + 2, f.z);
        atomicAdd(srow + 3, f.w);
        if (lane == 0) {
            const float old = atomicAdd(&g_counts[l], 1.0f);
            g_owner[w] = (old == 0.0f) ? 1 : 0;
        }

        const float dx = f.x - c.x, dy = f.y - c.y, dz = f.z - c.z, dw = f.w - c.w;
        v = dx * dx + dy * dy + dz * dz + dw * dw;
    }

    #pragma unroll
    for (int o = 16; o > 0; o >>= 1)
        v += __shfl_down_sync(0xffffffffu, v, o);
    if (lane == 0) s_part[wib] = v;
    __syncthreads();
    if (threadIdx.x == 0) {
        float tot = 0.0f;
        #pragma unroll
        for (int i = 0; i < 8; i++) tot += s_part[i];
        atomicAdd(&g_loss, (double)tot);
    }
}

// ---------------------------------------------------------------------------
// K2: PURE bulk shifted copy, warp-interleaved 2 quads/thread so that EVERY
// LDG.128 / STG.128 is perfectly coalesced (lane stride 16 B = 4 full 128 B
// lines per instruction). A warp owns 64 consecutive quads, base = 64*warp.
// Lane k handles quads qa = base+k and qb = base+32+k:
//   dst[qa] = { w(qa-1), A.xyz }  straddle: shfl_up(A.w); lane0 -> __ldg
//   dst[qb] = { w(qb-1), B.xyz }  straddle: shfl_up(B.w); lane0 -> shfl(A.w,31)
// Evict-first hints: the 1 GB stream is touch-once.
// Global quad 0 writes head out[1..3]; that thread also writes tail out[N].
// ---------------------------------------------------------------------------
__global__ void k_copy(const float* __restrict__ c, float* __restrict__ out)
{
    const int    gid  = blockIdx.x * blockDim.x + threadIdx.x;
    const size_t wrp  = (size_t)(gid >> 5);
    const int    lane = gid & 31;
    const size_t base = wrp * 64;
    const size_t qa   = base + lane;
    const size_t qb   = base + 32 + lane;

    const float4 A = __ldcs(reinterpret_cast<const float4*>(c) + qa);
    const float4 B = __ldcs(reinterpret_cast<const float4*>(c) + qb);

    float pwA = __shfl_up_sync(0xffffffffu, A.w, 1);       // w of quad qa-1
    float pwB = __shfl_up_sync(0xffffffffu, B.w, 1);       // w of quad qb-1
    const float a31 = __shfl_sync(0xffffffffu, A.w, 31);   // w of quad base+31
    if (lane == 0) {
        pwB = a31;
        if (base > 0) pwA = __ldg(c + 4 * base - 1);       // prev warp's last elem
    }

    if (qa == 0) {
        out[1] = A.x; out[2] = A.y; out[3] = A.z;
        out[N_ELEMS] = c[N_ELEMS - 1];                     // tail element
    } else {
        __stcs(reinterpret_cast<float4*>(out) + qa, make_float4(pwA, A.x, A.y, A.z));
    }
    __stcs(reinterpret_cast<float4*>(out) + qb, make_float4(pwB, B.x, B.y, B.z));
}

// ---------------------------------------------------------------------------
// K3 (after join): owner warps overwrite their class row with the momentum
// update using dst-ALIGNED float4 stores. Lane k computes val = elems
// 4k..4k+3 and stores out quad (32l + k) = {val[4k-1] via shfl, val[4k..4k+2]}
// covering out[128l+4k .. +3] = row elems 4k-1..4k+2. Lane 0 skips the vector
// store and writes elems 0..2 scalar; lane 31 writes elem 127 scalar.
// Coverage: 0..2 | 3..126 | 127 — complete, disjoint from neighboring rows.
// Then CLEAR the scratch consumed. Thread 0 emits loss + resets accumulator.
//   new_c = (1-ALPHA)*c + (ALPHA/cnt)*sum
// ---------------------------------------------------------------------------
__global__ void k_update(const float* __restrict__ centers,
                         const int*   __restrict__ labels,
                         float*       __restrict__ out)
{
    const int gid  = blockIdx.x * blockDim.x + threadIdx.x;
    const int w    = gid >> 5;
    const int lane = gid & 31;

    if (gid == 0) {
        out[0] = (float)(g_loss / (2.0 * (double)BATCH));
        g_loss = 0.0;
    }
    if (w >= BATCH) return;
    if (!g_owner[w]) return;                 // warp-uniform branch

    const int l = labels[w];
    const float cnt = g_counts[l];
    const float k1  = 1.0f - ALPHA;
    const float k2  = ALPHA / fmaxf(cnt, 1.0f);

    const size_t q = (size_t)l * 32 + lane;
    const float4 c = reinterpret_cast<const float4*>(centers)[q];
    const float4 s = reinterpret_cast<const float4*>(g_sums)[q];

    float4 val;
    val.x = k1 * c.x + k2 * s.x;
    val.y = k1 * c.y + k2 * s.y;
    val.z = k1 * c.z + k2 * s.z;
    val.w = k1 * c.w + k2 * s.w;

    const float pw = __shfl_up_sync(0xffffffffu, val.w, 1);  // val[4k-1]

    const size_t row = 1 + (size_t)l * FEAT_DIM;             // out[] index of elem 0
    if (lane == 0) {
        out[row + 0] = val.x;                                 // elems 0,1,2
        out[row + 1] = val.y;
        out[row + 2] = val.z;
    } else {
        reinterpret_cast<float4*>(out)[q] =
            make_float4(pw, val.x, val.y, val.z);
    }
    if (lane == 31)
        out[row + 127] = val.w;                               // elem 127

    // clean-on-exit: restore zeroed scratch for the next replay
    reinterpret_cast<float4*>(g_sums)[q] = make_float4(0.f, 0.f, 0.f, 0.f);
    if (lane == 0) {
        g_counts[l] = 0.0f;
        g_owner[w]  = 0;
    }
}

// ---------------------------------------------------------------------------
// R7 topology (proven best): accum on a high-priority side stream concurrent
// with the single bulk copy; join; one update. All capture-safe.
// ---------------------------------------------------------------------------
extern "C" void kernel_launch(void* const* d_in, const int* in_sizes, int n_in,
                              void* d_out, int out_size)
{
    const float* features = (const float*)d_in[0];
    const float* centers  = (const float*)d_in[1];
    const int*   labels   = (const int*)d_in[2];
    float*       out      = (float*)d_out;

    (void)in_sizes; (void)n_in; (void)out_size;

    const int warps_grid = (BATCH * 32) / 256;          // 2048 blocks of 256
    const int copy_blocks = (int)(N_CWARPS * 32 / 256); // 62,500 blocks

    int prLo = 0, prHi = 0;
    cudaDeviceGetStreamPriorityRange(&prLo, &prHi);

    cudaStream_t s2;
    cudaEvent_t  eFork, eJoin;
    cudaStreamCreateWithPriority(&s2, cudaStreamNonBlocking, prHi);
    cudaEventCreateWithFlags(&eFork, cudaEventDisableTiming);
    cudaEventCreateWithFlags(&eJoin, cudaEventDisableTiming);

    // fork: side stream joins the capture graph via the event dependency
    cudaEventRecord(eFork, 0);
    cudaStreamWaitEvent(s2, eFork, 0);

    k_accum<<<warps_grid, 256, 0, s2>>>(features, centers, labels);     // side
    k_copy <<<copy_blocks, 256>>>(centers, out);                        // main

    // join: main stream waits for accum before the update
    cudaEventRecord(eJoin, s2);
    cudaStreamWaitEvent(0, eJoin, 0);

    k_update<<<warps_grid, 256>>>(centers, labels, out);

    cudaEventDestroy(eFork);
    cudaEventDestroy(eJoin);
    cudaStreamDestroy(s2);
}

// round 14
// speedup vs baseline: 1.1496x; 1.0183x over previous
#include <cuda_runtime.h>
#include <cstddef>

#define NUM_CLASSES 1000000
#define FEAT_DIM    128
#define BATCH       16384
#define ALPHA       0.5f

#define N_ELEMS   ((size_t)NUM_CLASSES * FEAT_DIM)   // 128,000,000
#define N_QUADS   (N_ELEMS / 4)                       // 32,000,000
#define N_PAIRS   (N_QUADS / 2)                       // 16,000,000 (2 quads/thread)

// 7/8-ish split, both segments divisible by 256 threads/block.
#define P_A       14080000                            // pairs in copy_A (55000 blocks)
#define P_B       (N_PAIRS - P_A)                     // 1,920,000 pairs (7500 blocks)
// copy_A writes out elems [1 .. 4*2*P_A]; row l complete iff 128l+128 <= 8*P_A
#define L_SPLIT   880000                              // update_lo: l < L_SPLIT

// Scratch. .bss => zero-initialized at load; clean-on-exit in k_update
// restores zeroed state for the next graph replay.
__device__ float  g_sums[N_ELEMS];      // 512 MB static bss
__device__ float  g_counts[NUM_CLASSES];
__device__ int    g_owner[BATCH];       // 1 if batch elem is unique owner of its label
__device__ double g_loss;

// ---------------------------------------------------------------------------
// K1 (side stream, overlapped with copy_A): scatter features into per-class
// sums + counts, accumulate loss (block reduction -> 1 double atomic/block),
// elect one owner warp per distinct label.
// One warp per batch element; lane k owns feature quad k.
// ---------------------------------------------------------------------------
__global__ void k_accum(const float* __restrict__ features,
                        const float* __restrict__ centers,
                        const int*   __restrict__ labels)
{
    const int gid  = blockIdx.x * blockDim.x + threadIdx.x;
    const int w    = gid >> 5;
    const int lane = gid & 31;
    const int wib  = threadIdx.x >> 5;

    __shared__ float s_part[8];

    float v = 0.0f;
    if (w < BATCH) {
        const int l = labels[w];
        const float4 f = reinterpret_cast<const float4*>(features)[(size_t)w * 32 + lane];
        const float4 c = reinterpret_cast<const float4*>(centers )[(size_t)l * 32 + lane];

        float* srow = g_sums + (size_t)l * FEAT_DIM + lane * 4;
        atomicAdd(srow + 0, f.x);
        atomicAdd(srow + 1, f.y);
        atomicAdd(srow + 2, f.z);
        atomicAdd(srow + 3, f.w);
        if (lane == 0) {
            const float old = atomicAdd(&g_counts[l], 1.0f);
            g_owner[w] = (old == 0.0f) ? 1 : 0;
        }

        const float dx = f.x - c.x, dy = f.y - c.y, dz = f.z - c.z, dw = f.w - c.w;
        v = dx * dx + dy * dy + dz * dz + dw * dw;
    }

    #pragma unroll
    for (int o = 16; o > 0; o >>= 1)
        v += __shfl_down_sync(0xffffffffu, v, o);
    if (lane == 0) s_part[wib] = v;
    __syncthreads();
    if (threadIdx.x == 0) {
        float tot = 0.0f;
        #pragma unroll
        for (int i = 0; i < 8; i++) tot += s_part[i];
        atomicAdd(&g_loss, (double)tot);
    }
}

// ---------------------------------------------------------------------------
// K2: PURE bulk shifted copy (exact R11 winner: 2 sequential quads / thread),
// over pair range [base, base+count). Thread p owns src quads 2p, 2p+1:
//   dst[2p]   = { c[8p-1], b0.xyz }   (straddle from prev thread / shfl)
//   dst[2p+1] = { b0.w, b1.xyz }      (straddle is local — free)
// Evict-first hints: the 1 GB stream is touch-once.
// p==0 (first segment only) writes head out[1..3] and tail out[N].
// ---------------------------------------------------------------------------
__global__ void k_copy(const float* __restrict__ c, float* __restrict__ out,
                       size_t base)
{
    const size_t p  = base + (size_t)blockIdx.x * blockDim.x + threadIdx.x;
    const float4 b0 = __ldcs(reinterpret_cast<const float4*>(c) + 2 * p);
    const float4 b1 = __ldcs(reinterpret_cast<const float4*>(c) + 2 * p + 1);

    float pw = __shfl_up_sync(0xffffffffu, b1.w, 1);   // prev thread's last elem
    if ((threadIdx.x & 31) == 0 && p > 0)
        pw = __ldg(c + 8 * p - 1);

    if (p == 0) {
        out[1] = b0.x; out[2] = b0.y; out[3] = b0.z;
        out[N_ELEMS] = c[N_ELEMS - 1];                 // tail element
    } else {
        __stcs(reinterpret_cast<float4*>(out) + 2 * p,
               make_float4(pw, b0.x, b0.y, b0.z));
    }
    __stcs(reinterpret_cast<float4*>(out) + 2 * p + 1,
           make_float4(b0.w, b1.x, b1.y, b1.z));
}

// ---------------------------------------------------------------------------
// K3: owner warps with label in [lo, hi) overwrite their class row with the
// momentum update using dst-ALIGNED float4 stores. Lane k computes val =
// elems 4k..4k+3, stores out quad (32l+k) = {val[4k-1] via shfl, val[4k..+2]}
// covering row elems 4k-1..4k+2. Lane 0 writes elems 0..2 scalar; lane 31
// writes elem 127 scalar. Coverage complete, disjoint from adjacent rows.
// Then CLEAR the scratch consumed (clean-on-exit for the next replay).
// emit_loss: thread 0 writes out[0] and resets the accumulator.
//   new_c = (1-ALPHA)*c + (ALPHA/cnt)*sum
// ---------------------------------------------------------------------------
__global__ void k_update(const float* __restrict__ centers,
                         const int*   __restrict__ labels,
                         float*       __restrict__ out,
                         int lo, int hi, int emit_loss)
{
    const int gid  = blockIdx.x * blockDim.x + threadIdx.x;
    const int w    = gid >> 5;
    const int lane = gid & 31;

    if (emit_loss && gid == 0) {
        out[0] = (float)(g_loss / (2.0 * (double)BATCH));
        g_loss = 0.0;
    }
    if (w >= BATCH) return;
    if (!g_owner[w]) return;                 // warp-uniform
    const int l = labels[w];
    if (l < lo || l >= hi) return;           // warp-uniform

    const float cnt = g_counts[l];
    const float k1  = 1.0f - ALPHA;
    const float k2  = ALPHA / fmaxf(cnt, 1.0f);

    const size_t q = (size_t)l * 32 + lane;
    const float4 c = reinterpret_cast<const float4*>(centers)[q];
    const float4 s = reinterpret_cast<const float4*>(g_sums)[q];

    float4 val;
    val.x = k1 * c.x + k2 * s.x;
    val.y = k1 * c.y + k2 * s.y;
    val.z = k1 * c.z + k2 * s.z;
    val.w = k1 * c.w + k2 * s.w;

    const float pw = __shfl_up_sync(0xffffffffu, val.w, 1);  // val[4k-1]

    const size_t row = 1 + (size_t)l * FEAT_DIM;             // out[] idx of elem 0
    if (lane == 0) {
        out[row + 0] = val.x;
        out[row + 1] = val.y;
        out[row + 2] = val.z;
    } else {
        reinterpret_cast<float4*>(out)[q] =
            make_float4(pw, val.x, val.y, val.z);
    }
    if (lane == 31)
        out[row + 127] = val.w;

    // clean-on-exit: restore zeroed scratch for the next replay
    reinterpret_cast<float4*>(g_sums)[q] = make_float4(0.f, 0.f, 0.f, 0.f);
    if (lane == 0) {
        g_counts[l] = 0.0f;
        g_owner[w]  = 0;
    }
}

// ---------------------------------------------------------------------------
// Pipelined topology, 7/8 + 1/8 split:
//   main:  copy_A(55000 blk) -> copy_B(7500 blk) -> (wait accum) update_hi -> join
//   side:  accum -> [eAcc] -> (wait copy_A) -> update_lo(+loss) -> [eSide]
// update_lo (87.5% of rows) hides under copy_B (~19 us); only update_hi
// (~12.5% of owner rows, ~2 us) is exposed. All capture-safe.
// ---------------------------------------------------------------------------
extern "C" void kernel_launch(void* const* d_in, const int* in_sizes, int n_in,
                              void* d_out, int out_size)
{
    const float* features = (const float*)d_in[0];
    const float* centers  = (const float*)d_in[1];
    const int*   labels   = (const int*)d_in[2];
    float*       out      = (float*)d_out;

    (void)in_sizes; (void)n_in; (void)out_size;

    const int warps_grid = (BATCH * 32) / 256;          // 2048 blocks of 256

    int prLo = 0, prHi = 0;
    cudaDeviceGetStreamPriorityRange(&prLo, &prHi);

    cudaStream_t s2;
    cudaEvent_t  eFork, eAcc, eCopyA, eSide;
    cudaStreamCreateWithPriority(&s2, cudaStreamNonBlocking, prHi);
    cudaEventCreateWithFlags(&eFork,  cudaEventDisableTiming);
    cudaEventCreateWithFlags(&eAcc,   cudaEventDisableTiming);
    cudaEventCreateWithFlags(&eCopyA, cudaEventDisableTiming);
    cudaEventCreateWithFlags(&eSide,  cudaEventDisableTiming);

    // fork side stream into the capture
    cudaEventRecord(eFork, 0);
    cudaStreamWaitEvent(s2, eFork, 0);

    // side: accumulate (hidden under copy_A)
    k_accum<<<warps_grid, 256, 0, s2>>>(features, centers, labels);
    cudaEventRecord(eAcc, s2);

    // main: bulk copy, segment A (7/8)
    k_copy<<<P_A / 256, 256>>>(centers, out, 0);
    cudaEventRecord(eCopyA, 0);

    // main: bulk copy, segment B (1/8)
    k_copy<<<P_B / 256, 256>>>(centers, out, (size_t)P_A);

    // side: update rows finished by copy_A (hidden under copy_B), emit loss
    cudaStreamWaitEvent(s2, eCopyA, 0);
    k_update<<<warps_grid, 256, 0, s2>>>(centers, labels, out,
                                         0, L_SPLIT, /*emit_loss=*/1);
    cudaEventRecord(eSide, s2);

    // main: remaining high-label rows (needs accum + copy_B); join side last
    cudaStreamWaitEvent(0, eAcc, 0);
    k_update<<<warps_grid, 256>>>(centers, labels, out,
                                  L_SPLIT, NUM_CLASSES, /*emit_loss=*/0);
    cudaStreamWaitEvent(0, eSide, 0);

    cudaEventDestroy(eFork);
    cudaEventDestroy(eAcc);
    cudaEventDestroy(eCopyA);
    cudaEventDestroy(eSide);
    cudaStreamDestroy(s2);
}